// round 1
// baseline (speedup 1.0000x reference)
#include <cuda_runtime.h>

#define Bn 32
#define Gn 512
#define Dn 128
#define Hn 4
#define NORMF 0.17677669529663687f   // 1/sqrt(32)

// Scratch (device globals — no allocation allowed)
__device__ float g_M[4][Bn][Hn][Dn];        // [map: p1,p2,d1,d2][b][h][d]
__device__ float g_A [Bn * Gn * 32];        // fc1 partial from u (i-side)
__device__ float g_Bv[Bn * Gn * 32];        // fc1 partial from v (j-side) + b1

__constant__ float cFC1W[16][32];
__constant__ float cFC1B[32];
__constant__ float cW2[32][32];
__constant__ float cB2[32];
__constant__ float cW3[32];
__constant__ float cB3[1];

// -------------------------------------------------------------------------
// prep1: per batch b, gather pickup/delivery rows, compute Q = q @ Wq (H,K),
// then fold into M[b,h,d] = NORM * sum_k Q[h,k] * Wk[h,d,k].
// grid = Bn blocks, 128 threads.
// -------------------------------------------------------------------------
__global__ void prep1(const float* __restrict__ h,
                      const int* __restrict__ pp,
                      const int* __restrict__ pd,
                      const float* __restrict__ Wq1,
                      const float* __restrict__ Wk1,
                      const float* __restrict__ Wq2,
                      const float* __restrict__ Wk2) {
    int b = blockIdx.x;
    int t = threadIdx.x;   // 0..127
    __shared__ float shp[Dn], shd[Dn];
    __shared__ float sQ[4][Hn][32];   // [p1,p2,d1,d2][h][k]

    int ip = pp[b], id = pd[b];
    shp[t] = h[(b * Gn + ip) * Dn + t];
    shd[t] = h[(b * Gn + id) * Dn + t];
    __syncthreads();

    int hh = t >> 5, k = t & 31;
    float q_p1 = 0.f, q_p2 = 0.f, q_d1 = 0.f, q_d2 = 0.f;
    #pragma unroll 4
    for (int d = 0; d < Dn; d++) {
        float w1 = Wq1[(hh * Dn + d) * 32 + k];
        float w2 = Wq2[(hh * Dn + d) * 32 + k];
        float xp = shp[d], xd = shd[d];
        q_p1 = fmaf(xp, w1, q_p1);
        q_p2 = fmaf(xp, w2, q_p2);
        q_d1 = fmaf(xd, w1, q_d1);
        q_d2 = fmaf(xd, w2, q_d2);
    }
    sQ[0][hh][k] = q_p1;
    sQ[1][hh][k] = q_p2;
    sQ[2][hh][k] = q_d1;
    sQ[3][hh][k] = q_d2;
    __syncthreads();

    // M[w][b][h][d]: 4 maps x 4 heads x 128 d = 2048 values; 512 (h,d) pairs
    for (int p = t; p < Hn * Dn; p += 128) {
        int mh = p >> 7, d = p & 127;
        float m1 = 0.f, m2 = 0.f, m3 = 0.f, m4 = 0.f;
        #pragma unroll
        for (int k2 = 0; k2 < 32; k2++) {
            float wk1 = Wk1[(mh * Dn + d) * 32 + k2];
            float wk2 = Wk2[(mh * Dn + d) * 32 + k2];
            m1 = fmaf(sQ[0][mh][k2], wk1, m1);   // M_p1 (pickup, Wk1)
            m2 = fmaf(sQ[1][mh][k2], wk2, m2);   // M_p2 (pickup, Wk2)
            m3 = fmaf(sQ[2][mh][k2], wk1, m3);   // M_d1 (delivery, Wk1)
            m4 = fmaf(sQ[3][mh][k2], wk2, m4);   // M_d2 (delivery, Wk2)
        }
        g_M[0][b][mh][d] = m1 * NORMF;
        g_M[1][b][mh][d] = m2 * NORMF;
        g_M[2][b][mh][d] = m3 * NORMF;
        g_M[3][b][mh][d] = m4 * NORMF;
    }
}

// -------------------------------------------------------------------------
// prep2: per (b,g) compute u[8] (i-side compat) and v[8] (j-side compat),
// then fold through fc1: A = u @ W1[0:8], Bv = v @ W1[8:16] + b1.
// grid = Bn blocks, 512 threads (one g each).
// -------------------------------------------------------------------------
__global__ void __launch_bounds__(Gn) prep2(const float* __restrict__ h,
                                            const int* __restrict__ rec) {
    int b = blockIdx.x;
    int g = threadIdx.x;
    __shared__ float sM[4][Hn][Dn];   // 2048 floats

    for (int idx = g; idx < 4 * Hn * Dn; idx += Gn) {
        int w = idx >> 9;
        int r = idx & 511;
        (&sM[0][0][0])[idx] = (&g_M[0][0][0][0])[(w * Bn + b) * (Hn * Dn) + r];
    }
    __syncthreads();

    int nb = rec[b * Gn + g];
    const float4* hrow = (const float4*)(h + (b * Gn + g) * Dn);
    const float4* nrow = (const float4*)(h + (b * Gn + nb) * Dn);

    float u[8], v[8];
    #pragma unroll
    for (int l = 0; l < 8; l++) { u[l] = 0.f; v[l] = 0.f; }

    #pragma unroll 4
    for (int d4 = 0; d4 < Dn / 4; d4++) {
        float4 xv = __ldg(hrow + d4);
        float4 yv = __ldg(nrow + d4);
        float xs[4] = {xv.x, xv.y, xv.z, xv.w};
        float ys[4] = {yv.x, yv.y, yv.z, yv.w};
        #pragma unroll
        for (int r = 0; r < 4; r++) {
            int d = d4 * 4 + r;
            #pragma unroll
            for (int hh = 0; hh < Hn; hh++) {
                u[hh]     = fmaf(xs[r], sM[0][hh][d], u[hh]);       // c_pp
                u[4 + hh] = fmaf(ys[r], sM[1][hh][d], u[4 + hh]);   // c_po
                v[hh]     = fmaf(xs[r], sM[2][hh][d], v[hh]);       // c_dp
                v[4 + hh] = fmaf(ys[r], sM[3][hh][d], v[4 + hh]);   // c_do
            }
        }
    }

    int base = (b * Gn + g) * 32;
    #pragma unroll
    for (int k = 0; k < 32; k++) {
        float a = 0.f;
        float bb = cFC1B[k];
        #pragma unroll
        for (int l = 0; l < 8; l++) {
            a  = fmaf(u[l], cFC1W[l][k], a);
            bb = fmaf(v[l], cFC1W[8 + l][k], bb);
        }
        g_A[base + k]  = a;
        g_Bv[base + k] = bb;
    }
}

// -------------------------------------------------------------------------
// main: out[b,i,j] = fc3(relu(fc2(relu(A[b,i] + Bv[b,j]))))
// grid = (Gn, Bn), 512 threads (one j each).
// -------------------------------------------------------------------------
__global__ void __launch_bounds__(Gn, 1) mlp_main(float* __restrict__ out) {
    int b = blockIdx.y;
    int i = blockIdx.x;
    int j = threadIdx.x;

    const float4* Ar = (const float4*)&g_A[(b * Gn + i) * 32];
    const float4* Br = (const float4*)&g_Bv[(b * Gn + j) * 32];

    float y1[32];
    #pragma unroll
    for (int q = 0; q < 8; q++) {
        float4 a = __ldg(Ar + q);
        float4 c = __ldg(Br + q);
        y1[4 * q + 0] = fmaxf(a.x + c.x, 0.f);
        y1[4 * q + 1] = fmaxf(a.y + c.y, 0.f);
        y1[4 * q + 2] = fmaxf(a.z + c.z, 0.f);
        y1[4 * q + 3] = fmaxf(a.w + c.w, 0.f);
    }

    float acc[32];
    #pragma unroll
    for (int k = 0; k < 32; k++) acc[k] = cB2[k];

    #pragma unroll
    for (int l = 0; l < 32; l++) {
        float y = y1[l];
        #pragma unroll
        for (int k = 0; k < 32; k++)
            acc[k] = fmaf(y, cW2[l][k], acc[k]);
    }

    float o = cB3[0];
    #pragma unroll
    for (int k = 0; k < 32; k++)
        o = fmaf(fmaxf(acc[k], 0.f), cW3[k], o);

    out[((size_t)(b * Gn + i)) * Gn + j] = o;
}

// -------------------------------------------------------------------------
extern "C" void kernel_launch(void* const* d_in, const int* in_sizes, int n_in,
                              void* d_out, int out_size) {
    const float* h   = (const float*)d_in[0];
    const int*   pp  = (const int*)  d_in[1];
    const int*   pd  = (const int*)  d_in[2];
    const int*   rec = (const int*)  d_in[3];
    const float* Wq1 = (const float*)d_in[4];
    const float* Wk1 = (const float*)d_in[5];
    const float* Wq2 = (const float*)d_in[6];
    const float* Wk2 = (const float*)d_in[7];

    cudaMemcpyToSymbolAsync(cFC1W, d_in[8],  16 * 32 * sizeof(float), 0, cudaMemcpyDeviceToDevice, 0);
    cudaMemcpyToSymbolAsync(cFC1B, d_in[9],  32 * sizeof(float),      0, cudaMemcpyDeviceToDevice, 0);
    cudaMemcpyToSymbolAsync(cW2,   d_in[10], 32 * 32 * sizeof(float), 0, cudaMemcpyDeviceToDevice, 0);
    cudaMemcpyToSymbolAsync(cB2,   d_in[11], 32 * sizeof(float),      0, cudaMemcpyDeviceToDevice, 0);
    cudaMemcpyToSymbolAsync(cW3,   d_in[12], 32 * sizeof(float),      0, cudaMemcpyDeviceToDevice, 0);
    cudaMemcpyToSymbolAsync(cB3,   d_in[13], 1 * sizeof(float),       0, cudaMemcpyDeviceToDevice, 0);

    prep1<<<Bn, 128>>>(h, pp, pd, Wq1, Wk1, Wq2, Wk2);
    prep2<<<Bn, Gn>>>(h, rec);
    mlp_main<<<dim3(Gn, Bn), Gn>>>((float*)d_out);
}